// round 4
// baseline (speedup 1.0000x reference)
#include <cuda_runtime.h>
#include <cuda_bf16.h>

// Problem constants (match reference)
#define WPIX 512.0f
#define HPIX 512.0f
#define S_MIN (1.0f / 30.0f)
#define S_MAX (1.0f / 0.75f)
#define MU_BORDER 1.05f
#define PI_APPROX 3.1416f

#define MAX_N 1024           // static scratch sizing; actual N = 512
#define TILE_PX 16.0f
#define TILES_X 32
#define TILES_Y 32
#define NUM_TILES (TILES_X * TILES_Y)
#define TILE_CAP MAX_N       // worst case: every gaussian overlaps a tile

// Per-gaussian precomputed data (centered pixel coords):
// g_ga[n]   = (gmx, gmy, Sx, Sy)
// g_gb[n]   = (cos(a), sin(a), sigmoid(opacity), 0)
// g_sh[n*7] = repacked rgbsh (27 floats + pad)
// g_bbox[n] = (xmin, xmax, ymin, ymax) in RAW pixel coords, margin-dilated
__device__ float4 g_ga[MAX_N];
__device__ float4 g_gb[MAX_N];
__device__ float4 g_sh[MAX_N * 7];
__device__ float4 g_bbox[MAX_N];

// Per-tile gaussian lists (deterministic, index-ascending)
__device__ int g_tile_list[NUM_TILES * TILE_CAP];
__device__ int g_tile_cnt[NUM_TILES];

__global__ void precompute_kernel(const float* __restrict__ rgbsh,
                                  const float* __restrict__ opacity,
                                  const float* __restrict__ mu,
                                  const float* __restrict__ scale,
                                  const float* __restrict__ angle,
                                  int N) {
    int n = blockIdx.x * blockDim.x + threadIdx.x;
    if (n >= N) return;

    float gmx = tanhf(mu[2 * n + 0]) * (MU_BORDER * WPIX * 0.5f);
    float gmy = tanhf(mu[2 * n + 1]) * (MU_BORDER * HPIX * 0.5f);
    float sx = fminf(fmaxf(scale[2 * n + 0], 0.0f), 1.0f) * (S_MAX - S_MIN) + S_MIN;
    float sy = fminf(fmaxf(scale[2 * n + 1], 0.0f), 1.0f) * (S_MAX - S_MIN) + S_MIN;
    g_ga[n] = make_float4(gmx, gmy, sx, sy);

    float alpha = tanhf(angle[n]) * PI_APPROX;
    float c, s;
    sincosf(alpha, &s, &c);
    float op = 1.0f / (1.0f + expf(-opacity[n]));
    g_gb[n] = make_float4(c, s, op, 0.0f);

    // Conservative AABB of the valid ellipse |S*(p-gm)| < 5, in RAW pixel coords.
    // valid requires |vx| < 5/Sx AND |vy| < 5/Sy (since d2 = (Sx*vx)^2+(Sy*vy)^2).
    float hx = 5.0f / sx + 0.05f;   // margin for fp rounding
    float hy = 5.0f / sy + 0.05f;
    float cx = gmx + WPIX * 0.5f;
    float cy = gmy + HPIX * 0.5f;
    g_bbox[n] = make_float4(cx - hx, cx + hx, cy - hy, cy + hy);

    // repack 27 SH coeffs into 7 float4
    float v[28];
#pragma unroll
    for (int m = 0; m < 27; ++m) v[m] = rgbsh[n * 27 + m];
    v[27] = 0.0f;
#pragma unroll
    for (int j = 0; j < 7; ++j)
        g_sh[n * 7 + j] = make_float4(v[4 * j], v[4 * j + 1], v[4 * j + 2], v[4 * j + 3]);
}

// One warp per tile: ordered (index-ascending) ballot compaction -> deterministic lists.
__global__ void build_lists_kernel(int N) {
    int warpsPerBlock = blockDim.x >> 5;
    int tile = blockIdx.x * warpsPerBlock + (threadIdx.x >> 5);
    if (tile >= NUM_TILES) return;
    int lane = threadIdx.x & 31;

    int tx = tile & (TILES_X - 1);
    int ty = tile >> 5;
    float x0 = tx * TILE_PX, x1 = x0 + TILE_PX;
    float y0 = ty * TILE_PX, y1 = y0 + TILE_PX;

    int base = tile * TILE_CAP;
    int cnt = 0;
    int chunks = (N + 31) >> 5;
    for (int c = 0; c < chunks; ++c) {
        int g = (c << 5) + lane;
        bool ok = false;
        if (g < N) {
            float4 bb = g_bbox[g];
            ok = (bb.x <= x1) && (bb.y >= x0) && (bb.z <= y1) && (bb.w >= y0);
        }
        unsigned mask = __ballot_sync(0xFFFFFFFFu, ok);
        if (ok) {
            int off = __popc(mask & ((1u << lane) - 1u));
            g_tile_list[base + cnt + off] = g;
        }
        cnt += __popc(mask);
    }
    if (lane == 0) g_tile_cnt[tile] = cnt;
}

// One thread per ray: iterate only this ray's tile list.
__global__ __launch_bounds__(128)
void splat_kernel(const float* __restrict__ x,
                  float* __restrict__ out,
                  int B) {
    int ray = blockIdx.x * blockDim.x + threadIdx.x;
    if (ray >= B) return;

    float xr = x[2 * ray + 0];
    float yr = x[2 * ray + 1];
    float px = xr - (WPIX * 0.5f);
    float py = yr - (HPIX * 0.5f);

    int tx = min(TILES_X - 1, max(0, (int)(xr * (1.0f / TILE_PX))));
    int ty = min(TILES_Y - 1, max(0, (int)(yr * (1.0f / TILE_PX))));
    int tile = ty * TILES_X + tx;

    int cnt = g_tile_cnt[tile];
    const int* lst = &g_tile_list[tile * TILE_CAP];

    float sumR = 0.0f, sumG = 0.0f, sumB = 0.0f;

    for (int i = 0; i < cnt; ++i) {
        int n = lst[i];
        float4 ga = g_ga[n];
        float vx = px - ga.x;
        float vy = py - ga.y;
        float svx = vx * ga.z;
        float svy = vy * ga.w;
        float d2 = fmaf(svx, svx, svy * svy);
        if (d2 < 25.0f) {
            float4 gb = g_gb[n];
            float c = gb.x, s = gb.y;
            float w = __expf(-d2) * gb.z;

            // theta = atan2(rvx, rvy) where (rvx,rvy) = R * vnorm
            float rvx = c * vx - s * vy;
            float rvy = fmaf(s, vx, c * vy);
            float rn = rsqrtf(fmaf(rvx, rvx, fmaf(rvy, rvy, 1e-20f)));
            float s1 = rvx * rn;   // sin(theta)
            float c1 = rvy * rn;   // cos(theta)
            float s2 = 2.0f * s1 * c1;
            float c2 = fmaf(c1, c1, -s1 * s1);
            float s3 = fmaf(s1, c2, c1 * s2);
            float c3 = fmaf(c1, c2, -s1 * s2);
            float s4 = 2.0f * s2 * c2;
            float c4 = fmaf(c2, c2, -s2 * s2);

            const float4* shp = &g_sh[n * 7];
            float4 q0 = shp[0], q1 = shp[1], q2 = shp[2], q3 = shp[3];
            float4 q4 = shp[4], q5 = shp[5], q6 = shp[6];

            float aR = q0.x;
            aR = fmaf(s1, q0.w, aR); aR = fmaf(c1, q1.z, aR);
            aR = fmaf(s2, q2.y, aR); aR = fmaf(c2, q3.x, aR);
            aR = fmaf(s3, q3.w, aR); aR = fmaf(c3, q4.z, aR);
            aR = fmaf(s4, q5.y, aR); aR = fmaf(c4, q6.x, aR);
            float aG = q0.y;
            aG = fmaf(s1, q1.x, aG); aG = fmaf(c1, q1.w, aG);
            aG = fmaf(s2, q2.z, aG); aG = fmaf(c2, q3.y, aG);
            aG = fmaf(s3, q4.x, aG); aG = fmaf(c3, q4.w, aG);
            aG = fmaf(s4, q5.z, aG); aG = fmaf(c4, q6.y, aG);
            float aB = q0.z;
            aB = fmaf(s1, q1.y, aB); aB = fmaf(c1, q2.x, aB);
            aB = fmaf(s2, q2.w, aB); aB = fmaf(c2, q3.z, aB);
            aB = fmaf(s3, q4.y, aB); aB = fmaf(c3, q5.x, aB);
            aB = fmaf(s4, q5.w, aB); aB = fmaf(c4, q6.z, aB);

            float rR = __fdividef(1.0f, 1.0f + __expf(-aR));
            float rG = __fdividef(1.0f, 1.0f + __expf(-aG));
            float rB = __fdividef(1.0f, 1.0f + __expf(-aB));
            sumR = fmaf(w, rR, sumR);
            sumG = fmaf(w, rG, sumG);
            sumB = fmaf(w, rB, sumB);
        }
    }

    out[3 * ray + 0] = sumR;
    out[3 * ray + 1] = sumG;
    out[3 * ray + 2] = sumB;
}

extern "C" void kernel_launch(void* const* d_in, const int* in_sizes, int n_in,
                              void* d_out, int out_size) {
    // metadata order: x, rgbsh, opacity, mu, scale, angle
    const float* x       = (const float*)d_in[0];
    const float* rgbsh   = (const float*)d_in[1];
    const float* opacity = (const float*)d_in[2];
    const float* mu      = (const float*)d_in[3];
    const float* scale   = (const float*)d_in[4];
    const float* angle   = (const float*)d_in[5];
    float* out = (float*)d_out;

    int B = in_sizes[0] / 2;
    int N = in_sizes[2];

    precompute_kernel<<<(N + 255) / 256, 256>>>(rgbsh, opacity, mu, scale, angle, N);

    // 4 warps per block, one warp per tile
    build_lists_kernel<<<(NUM_TILES + 3) / 4, 128>>>(N);

    splat_kernel<<<(B + 127) / 128, 128>>>(x, out, B);
}

// round 5
// speedup vs baseline: 1.3194x; 1.3194x over previous
#include <cuda_runtime.h>
#include <cuda_bf16.h>

// Problem constants (match reference)
#define WPIX 512.0f
#define HPIX 512.0f
#define S_MIN (1.0f / 30.0f)
#define S_MAX (1.0f / 0.75f)
#define MU_BORDER 1.05f
#define PI_APPROX 3.1416f

#define MAX_N 1024           // static scratch sizing; actual N = 512
#define MAX_B 65536
#define TILE_PX 16.0f
#define TILES_X 32
#define TILES_Y 32
#define NUM_TILES (TILES_X * TILES_Y)
#define TILE_CAP MAX_N

// ---- per-gaussian precomputed data ----
__device__ float4 g_ga[MAX_N];          // (gmx, gmy, Sx, Sy), centered px coords
__device__ float4 g_gb[MAX_N];          // (cos a, sin a, sigmoid(op), 0)
__device__ float4 g_sh[MAX_N * 7];      // repacked 27 SH coeffs + pad

// ---- tile -> gaussian lists (deterministic, index-ascending) ----
__device__ int g_tile_list[NUM_TILES * TILE_CAP];
__device__ int g_tile_cnt[NUM_TILES];

// ---- ray binning (counting sort by tile) ----
__device__ int g_hist[NUM_TILES];       // .bss zero at load; re-zeroed by scan each call
__device__ int g_base[NUM_TILES];
__device__ int g_rank[MAX_B];
__device__ int g_perm[MAX_B];

__device__ __forceinline__ int tile_of(float xr, float yr) {
    int tx = min(TILES_X - 1, max(0, (int)(xr * (1.0f / TILE_PX))));
    int ty = min(TILES_Y - 1, max(0, (int)(yr * (1.0f / TILE_PX))));
    return ty * TILES_X + tx;
}

// ============================================================================
// K1: prep — 512 threads/block.
//   blocks [0, LIST_BLOCKS): build tile lists (redundant bbox in smem)
//   blocks [LIST_BLOCKS, LIST_BLOCKS+binBlocks): ray binning
//   last block: per-gaussian heavy precompute
// ============================================================================
#define LIST_BLOCKS 64   // 16 warps/block * 64 = 1024 tiles

__global__ __launch_bounds__(512)
void prep_kernel(const float* __restrict__ x,
                 const float* __restrict__ rgbsh,
                 const float* __restrict__ opacity,
                 const float* __restrict__ mu,
                 const float* __restrict__ scale,
                 const float* __restrict__ angle,
                 int B, int N, int binBlocks) {
    int bid = blockIdx.x;
    int tid = threadIdx.x;

    if (bid < LIST_BLOCKS) {
        // ---- tile-list building ----
        __shared__ float4 s_bbox[MAX_N];   // (xmin, xmax, ymin, ymax) raw px
        for (int n = tid; n < N; n += 512) {
            float gmx = tanhf(mu[2 * n + 0]) * (MU_BORDER * WPIX * 0.5f);
            float gmy = tanhf(mu[2 * n + 1]) * (MU_BORDER * HPIX * 0.5f);
            float sx = fminf(fmaxf(scale[2 * n + 0], 0.0f), 1.0f) * (S_MAX - S_MIN) + S_MIN;
            float sy = fminf(fmaxf(scale[2 * n + 1], 0.0f), 1.0f) * (S_MAX - S_MIN) + S_MIN;
            float hx = __fdividef(5.0f, sx) + 0.05f;
            float hy = __fdividef(5.0f, sy) + 0.05f;
            float cx = gmx + WPIX * 0.5f;
            float cy = gmy + HPIX * 0.5f;
            s_bbox[n] = make_float4(cx - hx, cx + hx, cy - hy, cy + hy);
        }
        __syncthreads();

        int warp = tid >> 5;
        int lane = tid & 31;
        int tile = bid * 16 + warp;   // 16 warps/block
        int tx = tile & (TILES_X - 1);
        int ty = tile >> 5;
        float x0 = tx * TILE_PX, x1 = x0 + TILE_PX;
        float y0 = ty * TILE_PX, y1 = y0 + TILE_PX;

        int base = tile * TILE_CAP;
        int cnt = 0;
        int chunks = (N + 31) >> 5;
        for (int c = 0; c < chunks; ++c) {
            int g = (c << 5) + lane;
            bool ok = false;
            if (g < N) {
                float4 bb = s_bbox[g];
                ok = (bb.x <= x1) && (bb.y >= x0) && (bb.z <= y1) && (bb.w >= y0);
            }
            unsigned m = __ballot_sync(0xFFFFFFFFu, ok);
            if (ok) {
                int off = __popc(m & ((1u << lane) - 1u));
                g_tile_list[base + cnt + off] = g;
            }
            cnt += __popc(m);
        }
        if (lane == 0) g_tile_cnt[tile] = cnt;
    } else if (bid < LIST_BLOCKS + binBlocks) {
        // ---- ray binning ----
        int r = (bid - LIST_BLOCKS) * 512 + tid;
        if (r < B) {
            float xr = x[2 * r + 0];
            float yr = x[2 * r + 1];
            int t = tile_of(xr, yr);
            g_rank[r] = atomicAdd(&g_hist[t], 1);
        }
    } else {
        // ---- per-gaussian heavy precompute (one block) ----
        for (int n = tid; n < N; n += 512) {
            float gmx = tanhf(mu[2 * n + 0]) * (MU_BORDER * WPIX * 0.5f);
            float gmy = tanhf(mu[2 * n + 1]) * (MU_BORDER * HPIX * 0.5f);
            float sx = fminf(fmaxf(scale[2 * n + 0], 0.0f), 1.0f) * (S_MAX - S_MIN) + S_MIN;
            float sy = fminf(fmaxf(scale[2 * n + 1], 0.0f), 1.0f) * (S_MAX - S_MIN) + S_MIN;
            g_ga[n] = make_float4(gmx, gmy, sx, sy);

            float alpha = tanhf(angle[n]) * PI_APPROX;
            float c, s;
            sincosf(alpha, &s, &c);
            float op = 1.0f / (1.0f + expf(-opacity[n]));
            g_gb[n] = make_float4(c, s, op, 0.0f);

            float v[28];
#pragma unroll
            for (int m = 0; m < 27; ++m) v[m] = rgbsh[n * 27 + m];
            v[27] = 0.0f;
#pragma unroll
            for (int j = 0; j < 7; ++j)
                g_sh[n * 7 + j] = make_float4(v[4 * j], v[4 * j + 1], v[4 * j + 2], v[4 * j + 3]);
        }
    }
}

// ============================================================================
// K2: exclusive scan of hist -> base; then re-zero hist (replay idempotence)
// ============================================================================
__global__ __launch_bounds__(NUM_TILES)
void scan_kernel() {
    __shared__ int buf[NUM_TILES];
    int t = threadIdx.x;
    int h = g_hist[t];
    buf[t] = h;
    __syncthreads();
#pragma unroll
    for (int off = 1; off < NUM_TILES; off <<= 1) {
        int v = (t >= off) ? buf[t - off] : 0;
        __syncthreads();
        buf[t] += v;
        __syncthreads();
    }
    g_base[t] = buf[t] - h;   // exclusive
    g_hist[t] = 0;
}

// ============================================================================
// K3: scatter — perm[base[tile]+rank[r]] = r
// ============================================================================
__global__ __launch_bounds__(128)
void scatter_kernel(const float* __restrict__ x, int B) {
    int r = blockIdx.x * 128 + threadIdx.x;
    if (r >= B) return;
    float xr = x[2 * r + 0];
    float yr = x[2 * r + 1];
    int t = tile_of(xr, yr);
    g_perm[g_base[t] + g_rank[r]] = r;
}

// ============================================================================
// K4: splat — thread s handles ray perm[s]; warp-coherent tile lists
// ============================================================================
__global__ __launch_bounds__(128)
void splat_kernel(const float* __restrict__ x,
                  float* __restrict__ out,
                  int B) {
    int s = blockIdx.x * 128 + threadIdx.x;
    if (s >= B) return;
    int ray = g_perm[s];

    float xr = x[2 * ray + 0];
    float yr = x[2 * ray + 1];
    float px = xr - (WPIX * 0.5f);
    float py = yr - (HPIX * 0.5f);

    int tile = tile_of(xr, yr);
    int cnt = g_tile_cnt[tile];
    const int* lst = &g_tile_list[tile * TILE_CAP];

    float sumR = 0.0f, sumG = 0.0f, sumB = 0.0f;

    for (int i = 0; i < cnt; ++i) {
        int n = lst[i];                   // warp-uniform (same tile) -> broadcast
        float4 ga = g_ga[n];
        float vx = px - ga.x;
        float vy = py - ga.y;
        float svx = vx * ga.z;
        float svy = vy * ga.w;
        float d2 = fmaf(svx, svx, svy * svy);
        if (d2 < 25.0f) {
            float4 gb = g_gb[n];
            float c = gb.x, sa = gb.y;
            float w = __expf(-d2) * gb.z;

            float rvx = c * vx - sa * vy;
            float rvy = fmaf(sa, vx, c * vy);
            float rn = rsqrtf(fmaf(rvx, rvx, fmaf(rvy, rvy, 1e-20f)));
            float s1 = rvx * rn;   // sin(theta)
            float c1 = rvy * rn;   // cos(theta)
            float s2 = 2.0f * s1 * c1;
            float c2 = fmaf(c1, c1, -s1 * s1);
            float s3 = fmaf(s1, c2, c1 * s2);
            float c3 = fmaf(c1, c2, -s1 * s2);
            float s4 = 2.0f * s2 * c2;
            float c4 = fmaf(c2, c2, -s2 * s2);

            const float4* shp = &g_sh[n * 7];
            float4 q0 = shp[0], q1 = shp[1], q2 = shp[2], q3 = shp[3];
            float4 q4 = shp[4], q5 = shp[5], q6 = shp[6];

            float aR = q0.x;
            aR = fmaf(s1, q0.w, aR); aR = fmaf(c1, q1.z, aR);
            aR = fmaf(s2, q2.y, aR); aR = fmaf(c2, q3.x, aR);
            aR = fmaf(s3, q3.w, aR); aR = fmaf(c3, q4.z, aR);
            aR = fmaf(s4, q5.y, aR); aR = fmaf(c4, q6.x, aR);
            float aG = q0.y;
            aG = fmaf(s1, q1.x, aG); aG = fmaf(c1, q1.w, aG);
            aG = fmaf(s2, q2.z, aG); aG = fmaf(c2, q3.y, aG);
            aG = fmaf(s3, q4.x, aG); aG = fmaf(c3, q4.w, aG);
            aG = fmaf(s4, q5.z, aG); aG = fmaf(c4, q6.y, aG);
            float aB = q0.z;
            aB = fmaf(s1, q1.y, aB); aB = fmaf(c1, q2.x, aB);
            aB = fmaf(s2, q2.w, aB); aB = fmaf(c2, q3.z, aB);
            aB = fmaf(s3, q4.y, aB); aB = fmaf(c3, q5.x, aB);
            aB = fmaf(s4, q5.w, aB); aB = fmaf(c4, q6.z, aB);

            float rR = __fdividef(1.0f, 1.0f + __expf(-aR));
            float rG = __fdividef(1.0f, 1.0f + __expf(-aG));
            float rB = __fdividef(1.0f, 1.0f + __expf(-aB));
            sumR = fmaf(w, rR, sumR);
            sumG = fmaf(w, rG, sumG);
            sumB = fmaf(w, rB, sumB);
        }
    }

    out[3 * ray + 0] = sumR;
    out[3 * ray + 1] = sumG;
    out[3 * ray + 2] = sumB;
}

extern "C" void kernel_launch(void* const* d_in, const int* in_sizes, int n_in,
                              void* d_out, int out_size) {
    // metadata order: x, rgbsh, opacity, mu, scale, angle
    const float* x       = (const float*)d_in[0];
    const float* rgbsh   = (const float*)d_in[1];
    const float* opacity = (const float*)d_in[2];
    const float* mu      = (const float*)d_in[3];
    const float* scale   = (const float*)d_in[4];
    const float* angle   = (const float*)d_in[5];
    float* out = (float*)d_out;

    int B = in_sizes[0] / 2;
    int N = in_sizes[2];

    int binBlocks = (B + 511) / 512;
    int grid1 = LIST_BLOCKS + binBlocks + 1;
    prep_kernel<<<grid1, 512>>>(x, rgbsh, opacity, mu, scale, angle, B, N, binBlocks);

    scan_kernel<<<1, NUM_TILES>>>();

    scatter_kernel<<<(B + 127) / 128, 128>>>(x, B);

    splat_kernel<<<(B + 127) / 128, 128>>>(x, out, B);
}

// round 6
// speedup vs baseline: 1.8632x; 1.4122x over previous
#include <cuda_runtime.h>
#include <cuda_bf16.h>

// Problem constants (match reference)
#define WPIX 512.0f
#define HPIX 512.0f
#define S_MIN (1.0f / 30.0f)
#define S_MAX (1.0f / 0.75f)
#define MU_BORDER 1.05f
#define PI_APPROX 3.1416f

#define MAX_N 1024           // static scratch sizing; actual N = 512
#define MAX_B 65536
#define TILE_PX 16.0f
#define TILES_X 32
#define TILES_Y 32
#define NUM_TILES (TILES_X * TILES_Y)
#define TILE_CAP MAX_N
#define GC 64                // gaussians staged per smem chunk

// ---- per-gaussian precomputed data ----
__device__ float4 g_ga[MAX_N];          // (gmx, gmy, Sx, Sy), centered px coords
__device__ float4 g_gb[MAX_N];          // (cos a, sin a, sigmoid(op), 0)
__device__ float4 g_sh[MAX_N * 7];      // repacked 27 SH coeffs + pad

// ---- tile -> gaussian lists (deterministic, index-ascending) ----
__device__ int g_tile_list[NUM_TILES * TILE_CAP];
__device__ int g_tile_cnt[NUM_TILES];

// ---- ray binning (counting sort by tile) ----
__device__ int g_hist[NUM_TILES];       // .bss zero at load; re-zeroed by splat each call
__device__ int g_base[NUM_TILES];
__device__ int g_rank[MAX_B];
__device__ int g_perm[MAX_B];

__device__ __forceinline__ int tile_of(float xr, float yr) {
    int tx = min(TILES_X - 1, max(0, (int)(xr * (1.0f / TILE_PX))));
    int ty = min(TILES_Y - 1, max(0, (int)(yr * (1.0f / TILE_PX))));
    return ty * TILES_X + tx;
}

// ============================================================================
// K1: prep — 512 threads/block.
//   blocks [0, LIST_BLOCKS): build tile lists (redundant bbox in smem)
//   blocks [LIST_BLOCKS, LIST_BLOCKS+binBlocks): ray binning (hist + rank)
//   last block: per-gaussian heavy precompute
// ============================================================================
#define LIST_BLOCKS 64   // 16 warps/block * 64 = 1024 tiles

__global__ __launch_bounds__(512)
void prep_kernel(const float* __restrict__ x,
                 const float* __restrict__ rgbsh,
                 const float* __restrict__ opacity,
                 const float* __restrict__ mu,
                 const float* __restrict__ scale,
                 const float* __restrict__ angle,
                 int B, int N, int binBlocks) {
    int bid = blockIdx.x;
    int tid = threadIdx.x;

    if (bid < LIST_BLOCKS) {
        __shared__ float4 s_bbox[MAX_N];   // (xmin, xmax, ymin, ymax) raw px
        for (int n = tid; n < N; n += 512) {
            float gmx = tanhf(mu[2 * n + 0]) * (MU_BORDER * WPIX * 0.5f);
            float gmy = tanhf(mu[2 * n + 1]) * (MU_BORDER * HPIX * 0.5f);
            float sx = fminf(fmaxf(scale[2 * n + 0], 0.0f), 1.0f) * (S_MAX - S_MIN) + S_MIN;
            float sy = fminf(fmaxf(scale[2 * n + 1], 0.0f), 1.0f) * (S_MAX - S_MIN) + S_MIN;
            float hx = __fdividef(5.0f, sx) + 0.05f;
            float hy = __fdividef(5.0f, sy) + 0.05f;
            float cx = gmx + WPIX * 0.5f;
            float cy = gmy + HPIX * 0.5f;
            s_bbox[n] = make_float4(cx - hx, cx + hx, cy - hy, cy + hy);
        }
        __syncthreads();

        int warp = tid >> 5;
        int lane = tid & 31;
        int tile = bid * 16 + warp;   // 16 warps/block
        int tx = tile & (TILES_X - 1);
        int ty = tile >> 5;
        float x0 = tx * TILE_PX, x1 = x0 + TILE_PX;
        float y0 = ty * TILE_PX, y1 = y0 + TILE_PX;

        int base = tile * TILE_CAP;
        int cnt = 0;
        int chunks = (N + 31) >> 5;
        for (int c = 0; c < chunks; ++c) {
            int g = (c << 5) + lane;
            bool ok = false;
            if (g < N) {
                float4 bb = s_bbox[g];
                ok = (bb.x <= x1) && (bb.y >= x0) && (bb.z <= y1) && (bb.w >= y0);
            }
            unsigned m = __ballot_sync(0xFFFFFFFFu, ok);
            if (ok) {
                int off = __popc(m & ((1u << lane) - 1u));
                g_tile_list[base + cnt + off] = g;
            }
            cnt += __popc(m);
        }
        if (lane == 0) g_tile_cnt[tile] = cnt;
    } else if (bid < LIST_BLOCKS + binBlocks) {
        int r = (bid - LIST_BLOCKS) * 512 + tid;
        if (r < B) {
            float xr = x[2 * r + 0];
            float yr = x[2 * r + 1];
            int t = tile_of(xr, yr);
            g_rank[r] = atomicAdd(&g_hist[t], 1);
        }
    } else {
        for (int n = tid; n < N; n += 512) {
            float gmx = tanhf(mu[2 * n + 0]) * (MU_BORDER * WPIX * 0.5f);
            float gmy = tanhf(mu[2 * n + 1]) * (MU_BORDER * HPIX * 0.5f);
            float sx = fminf(fmaxf(scale[2 * n + 0], 0.0f), 1.0f) * (S_MAX - S_MIN) + S_MIN;
            float sy = fminf(fmaxf(scale[2 * n + 1], 0.0f), 1.0f) * (S_MAX - S_MIN) + S_MIN;
            g_ga[n] = make_float4(gmx, gmy, sx, sy);

            float alpha = tanhf(angle[n]) * PI_APPROX;
            float c, s;
            sincosf(alpha, &s, &c);
            float op = 1.0f / (1.0f + expf(-opacity[n]));
            g_gb[n] = make_float4(c, s, op, 0.0f);

            float v[28];
#pragma unroll
            for (int m = 0; m < 27; ++m) v[m] = rgbsh[n * 27 + m];
            v[27] = 0.0f;
#pragma unroll
            for (int j = 0; j < 7; ++j)
                g_sh[n * 7 + j] = make_float4(v[4 * j], v[4 * j + 1], v[4 * j + 2], v[4 * j + 3]);
        }
    }
}

// ============================================================================
// K2: scan_scatter — every block redundantly scans the 1024-bin histogram in
// smem (cheap), then scatters its 1024-ray slice: perm[base[t]+rank[r]] = r.
// Block 0 also publishes g_base for splat.
// ============================================================================
__global__ __launch_bounds__(NUM_TILES)
void scan_scatter_kernel(const float* __restrict__ x, int B) {
    __shared__ int buf[NUM_TILES];
    __shared__ int sbase[NUM_TILES];
    int t = threadIdx.x;
    int h = g_hist[t];
    buf[t] = h;
    __syncthreads();
#pragma unroll
    for (int off = 1; off < NUM_TILES; off <<= 1) {
        int v = (t >= off) ? buf[t - off] : 0;
        __syncthreads();
        buf[t] += v;
        __syncthreads();
    }
    sbase[t] = buf[t] - h;   // exclusive
    if (blockIdx.x == 0) g_base[t] = sbase[t];
    __syncthreads();

    int r = blockIdx.x * NUM_TILES + t;
    if (r < B) {
        float xr = x[2 * r + 0];
        float yr = x[2 * r + 1];
        int tr = tile_of(xr, yr);
        g_perm[sbase[tr] + g_rank[r]] = r;
    }
}

// ============================================================================
// K3: splat — one block per tile; smem-staged gaussian data; zeroes hist.
// ============================================================================
#define SPLAT_THREADS 128

__global__ __launch_bounds__(SPLAT_THREADS)
void splat_kernel(const float* __restrict__ x,
                  float* __restrict__ out,
                  int B) {
    __shared__ float4 s_ga[GC];
    __shared__ float4 s_gb[GC];
    __shared__ float4 s_sh[GC][8];   // 7 used + 1 pad

    int t = blockIdx.x;
    int tid = threadIdx.x;

    if (tid == 0) g_hist[t] = 0;     // replay idempotence

    int base = g_base[t];
    int rayEnd = (t == NUM_TILES - 1) ? B : g_base[t + 1];
    int rayCount = rayEnd - base;
    if (rayCount == 0) return;       // block-uniform

    int cnt = g_tile_cnt[t];
    int lbase = t * TILE_CAP;

    for (int r0 = 0; r0 < rayCount; r0 += SPLAT_THREADS) {
        int myIdx = r0 + tid;
        bool active = myIdx < rayCount;
        int ray = 0;
        float px = 0.0f, py = 0.0f;
        if (active) {
            ray = g_perm[base + myIdx];
            px = x[2 * ray + 0] - (WPIX * 0.5f);
            py = x[2 * ray + 1] - (HPIX * 0.5f);
        }
        float sumR = 0.0f, sumG = 0.0f, sumB = 0.0f;

        for (int c0 = 0; c0 < cnt; c0 += GC) {
            int m = min(GC, cnt - c0);
            __syncthreads();   // protect smem from previous chunk/batch readers
            // stage ga/gb
            for (int i = tid; i < m; i += SPLAT_THREADS) {
                int n = g_tile_list[lbase + c0 + i];
                s_ga[i] = g_ga[n];
                s_gb[i] = g_gb[n];
            }
            // stage sh (7 float4 per gaussian)
            for (int i = tid; i < m * 8; i += SPLAT_THREADS) {
                int sl = i >> 3, j = i & 7;
                if (j < 7) {
                    int n = g_tile_list[lbase + c0 + sl];
                    s_sh[sl][j] = g_sh[n * 7 + j];
                }
            }
            __syncthreads();

            if (active) {
                for (int i = 0; i < m; ++i) {
                    float4 ga = s_ga[i];
                    float vx = px - ga.x;
                    float vy = py - ga.y;
                    float svx = vx * ga.z;
                    float svy = vy * ga.w;
                    float d2 = fmaf(svx, svx, svy * svy);
                    if (d2 < 25.0f) {
                        float4 gb = s_gb[i];
                        float c = gb.x, sa = gb.y;
                        float w = __expf(-d2) * gb.z;

                        float rvx = c * vx - sa * vy;
                        float rvy = fmaf(sa, vx, c * vy);
                        float rn = rsqrtf(fmaf(rvx, rvx, fmaf(rvy, rvy, 1e-20f)));
                        float s1 = rvx * rn;   // sin(theta)
                        float c1 = rvy * rn;   // cos(theta)
                        float s2 = 2.0f * s1 * c1;
                        float c2 = fmaf(c1, c1, -s1 * s1);
                        float s3 = fmaf(s1, c2, c1 * s2);
                        float c3 = fmaf(c1, c2, -s1 * s2);
                        float s4 = 2.0f * s2 * c2;
                        float c4 = fmaf(c2, c2, -s2 * s2);

                        float4 q0 = s_sh[i][0], q1 = s_sh[i][1], q2 = s_sh[i][2];
                        float4 q3 = s_sh[i][3], q4 = s_sh[i][4], q5 = s_sh[i][5];
                        float4 q6 = s_sh[i][6];

                        float aR = q0.x;
                        aR = fmaf(s1, q0.w, aR); aR = fmaf(c1, q1.z, aR);
                        aR = fmaf(s2, q2.y, aR); aR = fmaf(c2, q3.x, aR);
                        aR = fmaf(s3, q3.w, aR); aR = fmaf(c3, q4.z, aR);
                        aR = fmaf(s4, q5.y, aR); aR = fmaf(c4, q6.x, aR);
                        float aG = q0.y;
                        aG = fmaf(s1, q1.x, aG); aG = fmaf(c1, q1.w, aG);
                        aG = fmaf(s2, q2.z, aG); aG = fmaf(c2, q3.y, aG);
                        aG = fmaf(s3, q4.x, aG); aG = fmaf(c3, q4.w, aG);
                        aG = fmaf(s4, q5.z, aG); aG = fmaf(c4, q6.y, aG);
                        float aB = q0.z;
                        aB = fmaf(s1, q1.y, aB); aB = fmaf(c1, q2.x, aB);
                        aB = fmaf(s2, q2.w, aB); aB = fmaf(c2, q3.z, aB);
                        aB = fmaf(s3, q4.y, aB); aB = fmaf(c3, q5.x, aB);
                        aB = fmaf(s4, q5.w, aB); aB = fmaf(c4, q6.z, aB);

                        float rR = __fdividef(1.0f, 1.0f + __expf(-aR));
                        float rG = __fdividef(1.0f, 1.0f + __expf(-aG));
                        float rB = __fdividef(1.0f, 1.0f + __expf(-aB));
                        sumR = fmaf(w, rR, sumR);
                        sumG = fmaf(w, rG, sumG);
                        sumB = fmaf(w, rB, sumB);
                    }
                }
            }
        }

        if (active) {
            out[3 * ray + 0] = sumR;
            out[3 * ray + 1] = sumG;
            out[3 * ray + 2] = sumB;
        }
    }
}

extern "C" void kernel_launch(void* const* d_in, const int* in_sizes, int n_in,
                              void* d_out, int out_size) {
    // metadata order: x, rgbsh, opacity, mu, scale, angle
    const float* x       = (const float*)d_in[0];
    const float* rgbsh   = (const float*)d_in[1];
    const float* opacity = (const float*)d_in[2];
    const float* mu      = (const float*)d_in[3];
    const float* scale   = (const float*)d_in[4];
    const float* angle   = (const float*)d_in[5];
    float* out = (float*)d_out;

    int B = in_sizes[0] / 2;
    int N = in_sizes[2];

    int binBlocks = (B + 511) / 512;
    prep_kernel<<<LIST_BLOCKS + binBlocks + 1, 512>>>(x, rgbsh, opacity, mu, scale, angle, B, N, binBlocks);

    scan_scatter_kernel<<<(B + NUM_TILES - 1) / NUM_TILES, NUM_TILES>>>(x, B);

    splat_kernel<<<NUM_TILES, SPLAT_THREADS>>>(x, out, B);
}